// round 7
// baseline (speedup 1.0000x reference)
#include <cuda_runtime.h>

// ---------------------------------------------------------------------------
// QuantumClassifier: 4 lanes per sample, fully convergent.
//   lane bit0 (h)    = which half of the 4q state (amplitudes with bit0 = h)
//   lane bit1 (role) = Q circuit (0) or V circuit (1)
// Gates on wires 1-3 are local on 8 amps; wire-0 gates use symmetric
// shfl_xor(1) formulas. Score crosses Q->V via shfl_xor(2).
// 2048 warps (3.46/SMSP) with ~half the per-thread chain of the 2-lane version.
// ---------------------------------------------------------------------------

struct Cx { float r, i; };

#define PI_F  3.14159265358979f
#define SROWS 64      // samples per block
#define TPB   256     // 4 threads per sample

__device__ __forceinline__ Cx shflx(Cx v, int m) {
    return Cx{ __shfl_xor_sync(0xffffffffu, v.r, m),
               __shfl_xor_sync(0xffffffffu, v.i, m) };
}

// ======================= full 16-amp primitives (K-state sim only) =========
template<int W>
__device__ __forceinline__ void ap1g(Cx* p, Cx u0, Cx u1, Cx u2, Cx u3) {
    constexpr int s = 8 >> W;
    #pragma unroll
    for (int i = 0; i < 16; ++i) if (!(i & s)) {
        Cx a = p[i], b = p[i + s];
        p[i]   = Cx{ u0.r*a.r - u0.i*a.i + u1.r*b.r - u1.i*b.i,
                     u0.r*a.i + u0.i*a.r + u1.r*b.i + u1.i*b.r };
        p[i+s] = Cx{ u2.r*a.r - u2.i*a.i + u3.r*b.r - u3.i*b.i,
                     u2.r*a.i + u2.i*a.r + u3.r*b.i + u3.i*b.r };
    }
}
template<int A, int B>
__device__ __forceinline__ void crxg(Cx* p, float c, float s) {
    constexpr int sa = 8 >> A, sb = 8 >> B;
    #pragma unroll
    for (int i = 0; i < 16; ++i) if ((i & sa) && !(i & sb)) {
        Cx a = p[i], b = p[i + sb];
        p[i]    = Cx{ c*a.r + s*b.i, c*a.i - s*b.r };
        p[i+sb] = Cx{ c*b.r + s*a.i, c*b.i - s*a.r };
    }
}
template<int A, int B>
__device__ __forceinline__ void cnotg(Cx* p) {
    constexpr int sa = 8 >> A, sb = 8 >> B;
    #pragma unroll
    for (int i = 0; i < 16; ++i) if ((i & sa) && !(i & sb)) {
        Cx t = p[i]; p[i] = p[i + sb]; p[i + sb] = t;
    }
}
template<int A, int B>
__device__ __forceinline__ void stage16(Cx* p, const float* g, int i) {
    Cx u0{g[8*i+0], g[8*i+1]}, u1{g[8*i+2], g[8*i+3]},
       u2{g[8*i+4], g[8*i+5]}, u3{g[8*i+6], g[8*i+7]};
    ap1g<A>(p, u0, u1, u2, u3);
    crxg<A, B>(p, g[64+2*i], g[64+2*i+1]);
    cnotg<A, B>(p);
}
__device__ __forceinline__ void init_qkv16(Cx* p, const float* g) {
    stage16<0,1>(p, g, 0); stage16<1,2>(p, g, 1); stage16<2,3>(p, g, 2); stage16<3,0>(p, g, 3);
    stage16<0,3>(p, g, 4); stage16<1,0>(p, g, 5); stage16<2,1>(p, g, 6); stage16<3,2>(p, g, 7);
}
template<int W>
__device__ __forceinline__ float expX16(const Cx* p) {
    constexpr int st = 8 >> W;
    float v = 0.f;
    #pragma unroll
    for (int i = 0; i < 16; ++i) if (!(i & st))
        v += p[i].r*p[i+st].r + p[i].i*p[i+st].i;
    return 2.f * v;
}

// ======================= split-state primitives (8 amps per lane) ==========
// lane h holds amplitudes i with bit0(i)==h; local index j = i & 7
// strides within j: wire1->4, wire2->2, wire3->1 (8 >> W)

template<int W>   // W in {1,2,3}
__device__ __forceinline__ void ap1_local(Cx* p, Cx u0, Cx u1, Cx u2, Cx u3) {
    constexpr int s = 8 >> W;
    #pragma unroll
    for (int j = 0; j < 8; ++j) if (!(j & s)) {
        Cx a = p[j], b = p[j + s];
        p[j]   = Cx{ u0.r*a.r - u0.i*a.i + u1.r*b.r - u1.i*b.i,
                     u0.r*a.i + u0.i*a.r + u1.r*b.i + u1.i*b.r };
        p[j+s] = Cx{ u2.r*a.r - u2.i*a.i + u3.r*b.r - u3.i*b.i,
                     u2.r*a.i + u2.i*a.r + u3.r*b.i + u3.i*b.r };
    }
}

// 1q gate on wire 0: out_lane0 = u00*local + u01*remote, out_lane1 = u11*local + u10*remote
__device__ __forceinline__ void ap1_w0(Cx* p, Cx u0, Cx u1, Cx u2, Cx u3, int h) {
    Cx q[8];
    #pragma unroll
    for (int j = 0; j < 8; ++j) q[j] = shflx(p[j], 1);
    Cx cl = h ? u3 : u0, cr = h ? u2 : u1;
    #pragma unroll
    for (int j = 0; j < 8; ++j) {
        Cx l = p[j], r = q[j];
        p[j] = Cx{ cl.r*l.r - cl.i*l.i + cr.r*r.r - cr.i*r.i,
                   cl.r*l.i + cl.i*l.r + cr.r*r.i + cr.i*r.r };
    }
}

// RX on wire 0 (symmetric form: out.r = c*l.r + s*r.i, out.i = c*l.i - s*r.r)
__device__ __forceinline__ void rx_w0(Cx* p, float c, float s) {
    Cx q[8];
    #pragma unroll
    for (int j = 0; j < 8; ++j) q[j] = shflx(p[j], 1);
    #pragma unroll
    for (int j = 0; j < 8; ++j)
        p[j] = Cx{ c*p[j].r + s*q[j].i, c*p[j].i - s*q[j].r };
}

template<int W>
__device__ __forceinline__ void rx_local(Cx* p, float c, float s) {
    constexpr int st = 8 >> W;
    #pragma unroll
    for (int j = 0; j < 8; ++j) if (!(j & st)) {
        Cx a = p[j], b = p[j + st];
        p[j]    = Cx{ c*a.r + s*b.i, c*a.i - s*b.r };
        p[j+st] = Cx{ c*b.r + s*a.i, c*b.i - s*a.r };
    }
}

template<int A, int B>   // A,B in {1,2,3}
__device__ __forceinline__ void crx_local(Cx* p, float c, float s) {
    constexpr int sa = 8 >> A, sb = 8 >> B;
    #pragma unroll
    for (int j = 0; j < 8; ++j) if ((j & sa) && !(j & sb)) {
        Cx a = p[j], b = p[j + sb];
        p[j]    = Cx{ c*a.r + s*b.i, c*a.i - s*b.r };
        p[j+sb] = Cx{ c*b.r + s*a.i, c*b.i - s*a.r };
    }
}

// CRX with control wire 0: lane h=1 applies RX(B), h=0 identity (via (1,0))
template<int B>
__device__ __forceinline__ void crx_ctrl0(Cx* p, float c, float s, int h) {
    float ce = h ? c : 1.f, se = h ? s : 0.f;
    constexpr int sb = 8 >> B;
    #pragma unroll
    for (int j = 0; j < 8; ++j) if (!(j & sb)) {
        Cx a = p[j], b = p[j + sb];
        p[j]    = Cx{ ce*a.r + se*b.i, ce*a.i - se*b.r };
        p[j+sb] = Cx{ ce*b.r + se*a.i, ce*b.i - se*a.r };
    }
}

// CRX with target wire 0 (symmetric cross-lane form), control A in {1,3}
template<int A>
__device__ __forceinline__ void crx_tgt0(Cx* p, float c, float s) {
    constexpr int sa = 8 >> A;
    #pragma unroll
    for (int j = 0; j < 8; ++j) if (j & sa) {
        Cx r = shflx(p[j], 1);
        p[j] = Cx{ c*p[j].r + s*r.i, c*p[j].i - s*r.r };
    }
}

template<int A, int B>
__device__ __forceinline__ void cnot_local(Cx* p) {
    constexpr int sa = 8 >> A, sb = 8 >> B;
    #pragma unroll
    for (int j = 0; j < 8; ++j) if ((j & sa) && !(j & sb)) {
        Cx t = p[j]; p[j] = p[j + sb]; p[j + sb] = t;
    }
}

// CNOT control wire 0: lane 1 swaps local pairs, lane 0 identity (selects)
template<int B>
__device__ __forceinline__ void cnot_ctrl0(Cx* p, int h) {
    constexpr int sb = 8 >> B;
    #pragma unroll
    for (int j = 0; j < 8; ++j) if (!(j & sb)) {
        Cx a = p[j], b = p[j + sb];
        p[j]      = h ? b : a;
        p[j + sb] = h ? a : b;
    }
}

// CNOT target wire 0: exchange with partner where control bit set
template<int A>
__device__ __forceinline__ void cnot_tgt0(Cx* p) {
    constexpr int sa = 8 >> A;
    #pragma unroll
    for (int j = 0; j < 8; ++j) if (j & sa) p[j] = shflx(p[j], 1);
}

// RZ wire 0: phase sign = lane h
__device__ __forceinline__ void rz0(Cx* p, float c, float s, int h) {
    float ss = h ? s : -s;
    #pragma unroll
    for (int j = 0; j < 8; ++j) {
        Cx a = p[j];
        p[j] = Cx{ c*a.r - ss*a.i, c*a.i + ss*a.r };
    }
}
template<int W>
__device__ __forceinline__ void rz_local(Cx* p, float c, float s) {
    constexpr int st = 8 >> W;
    #pragma unroll
    for (int j = 0; j < 8; ++j) {
        Cx a = p[j];
        float ss = (j & st) ? s : -s;
        p[j] = Cx{ c*a.r - ss*a.i, c*a.i + ss*a.r };
    }
}

template<int A, int B>
__device__ __forceinline__ void stage_split(Cx* p, const float* g, int i, int h) {
    Cx u0{g[8*i+0], g[8*i+1]}, u1{g[8*i+2], g[8*i+3]},
       u2{g[8*i+4], g[8*i+5]}, u3{g[8*i+6], g[8*i+7]};
    float c = g[64+2*i], s = g[64+2*i+1];
    if constexpr (A == 0) {
        ap1_w0(p, u0, u1, u2, u3, h);
        crx_ctrl0<B>(p, c, s, h);
        cnot_ctrl0<B>(p, h);
    } else if constexpr (B == 0) {
        ap1_local<A>(p, u0, u1, u2, u3);
        crx_tgt0<A>(p, c, s);
        cnot_tgt0<A>(p);
    } else {
        ap1_local<A>(p, u0, u1, u2, u3);
        crx_local<A, B>(p, c, s);
        cnot_local<A, B>(p);
    }
}

// wire-pair order: (0,1)(1,2)(2,3)(3,0)(0,3)(1,0)(2,1)(3,2)
__device__ __forceinline__ void init_qkv_split(Cx* p, const float* g, int h) {
    stage_split<0,1>(p, g, 0, h); stage_split<1,2>(p, g, 1, h);
    stage_split<2,3>(p, g, 2, h); stage_split<3,0>(p, g, 3, h);
    stage_split<0,3>(p, g, 4, h); stage_split<1,0>(p, g, 5, h);
    stage_split<2,1>(p, g, 6, h); stage_split<3,2>(p, g, 7, h);
}

// all 4 <Z_w>, <X_w> of the split state; result complete on BOTH lanes
__device__ __forceinline__ void measZX_split(const Cx* p, int h, float* z, float* x) {
    float mag[8];
    #pragma unroll
    for (int j = 0; j < 8; ++j) mag[j] = p[j].r*p[j].r + p[j].i*p[j].i;
    float ms = ((mag[0]+mag[1]) + (mag[2]+mag[3])) + ((mag[4]+mag[5]) + (mag[6]+mag[7]));
    float pz0 = h ? -ms : ms;
    float pz1 = ((mag[0]+mag[1]) + (mag[2]+mag[3])) - ((mag[4]+mag[5]) + (mag[6]+mag[7]));
    float pz2 = ((mag[0]+mag[1]) - (mag[2]+mag[3])) + ((mag[4]+mag[5]) - (mag[6]+mag[7]));
    float pz3 = ((mag[0]-mag[1]) + (mag[2]-mag[3])) + ((mag[4]-mag[5]) + (mag[6]-mag[7]));
    z[0] = pz0 + __shfl_xor_sync(0xffffffffu, pz0, 1);
    z[1] = pz1 + __shfl_xor_sync(0xffffffffu, pz1, 1);
    z[2] = pz2 + __shfl_xor_sync(0xffffffffu, pz2, 1);
    z[3] = pz3 + __shfl_xor_sync(0xffffffffu, pz3, 1);
    // X on wire 0: full dot with the partner half (same value on both lanes)
    {
        float px0 = 0.f;
        #pragma unroll
        for (int j = 0; j < 8; ++j) {
            Cx r = shflx(p[j], 1);
            px0 += p[j].r*r.r + p[j].i*r.i;
        }
        x[0] = 2.f * px0;
    }
    // X on wires 1-3: local pairs + partner partial
    float px1 = 0.f, px2 = 0.f, px3 = 0.f;
    #pragma unroll
    for (int j = 0; j < 8; ++j) {
        if (!(j & 4)) px1 += p[j].r*p[j+4].r + p[j].i*p[j+4].i;
        if (!(j & 2)) px2 += p[j].r*p[j+2].r + p[j].i*p[j+2].i;
        if (!(j & 1)) px3 += p[j].r*p[j+1].r + p[j].i*p[j+1].i;
    }
    x[1] = 2.f * (px1 + __shfl_xor_sync(0xffffffffu, px1, 1));
    x[2] = 2.f * (px2 + __shfl_xor_sync(0xffffffffu, px2, 1));
    x[3] = 2.f * (px3 + __shfl_xor_sync(0xffffffffu, px3, 1));
}

// one Rot+CRX stage of a gate table
__device__ __forceinline__ void build_stage(const float* rot, const float* crx,
                                            int s, float* g) {
    float phi = rot[3*s], th = rot[3*s+1], om = rot[3*s+2];
    float sa, ca, sb, cb, st2, ct2;
    sincosf(0.5f*(phi+om), &sa, &ca);
    sincosf(0.5f*(phi-om), &sb, &cb);
    sincosf(0.5f*th, &st2, &ct2);
    g[8*s+0] =  ca*ct2; g[8*s+1] = -sa*ct2;   // u00 = e^{-iA} cos
    g[8*s+2] = -cb*st2; g[8*s+3] = -sb*st2;   // u01 = -e^{+iB} sin
    g[8*s+4] =  cb*st2; g[8*s+5] = -sb*st2;   // u10 = e^{-iB} sin
    g[8*s+6] =  ca*ct2; g[8*s+7] =  sa*ct2;   // u11 = e^{+iA} cos
    float cc, sc; sincosf(0.5f*crx[s], &sc, &cc);
    g[64+2*s] = cc; g[64+2*s+1] = sc;
}

__global__ void __launch_bounds__(TPB)
qc_quad(const float* __restrict__ x1,
        const float* __restrict__ pre_w, const float* __restrict__ pre_b,
        const float* __restrict__ q_rot, const float* __restrict__ k_rot,
        const float* __restrict__ v_rot,
        const float* __restrict__ q_crx, const float* __restrict__ k_crx,
        const float* __restrict__ v_crx,
        const float* __restrict__ ln_w, const float* __restrict__ ln_b,
        const float* __restrict__ head_w, const float* __restrict__ head_b,
        float* __restrict__ out, int B)
{
    __shared__ __align__(16) float sg[3][80];        // Q / K / V gate tables
    __shared__ float sxk[4];                         // <X_w> of constant K state
    __shared__ __align__(16) float wsh[384];         // pre_w
    __shared__ __align__(16) float tile[SROWS][100]; // x1 tile (pad 100 = 25 f4)

    const int t = threadIdx.x;
    const int base = blockIdx.x * SROWS;
    const int rows = min(SROWS, B - base);

    if (t >= 224) {
        // warp 7: K table -> K simulation -> sxk  (overlaps other warps)
        if (t < 232) build_stage(k_rot, k_crx, t - 224, sg[1]);
        __syncwarp();
        if (t == 224) {
            Cx p[16];
            #pragma unroll
            for (int i = 0; i < 16; ++i) p[i] = Cx{0.f, 0.f};
            p[0] = Cx{1.f, 0.f};
            init_qkv16(p, sg[1]);
            sxk[0] = expX16<0>(p); sxk[1] = expX16<1>(p);
            sxk[2] = expX16<2>(p); sxk[3] = expX16<3>(p);
        }
    } else {
        if (t < 16) {
            int c = t >> 3, s = t & 7;            // c=0 -> Q, c=1 -> V
            build_stage(c ? v_rot : q_rot, c ? v_crx : q_crx, s, sg[c ? 2 : 0]);
        }
        const float4* x4 = reinterpret_cast<const float4*>(x1 + (size_t)base * 96);
        for (int f = t; f < rows * 24; f += 224) {
            float4 v = x4[f];
            int r = f / 24, c = f % 24;
            *reinterpret_cast<float4*>(&tile[r][4 * c]) = v;
        }
        for (int e = t; e < 384; e += 224) wsh[e] = pre_w[e];
    }
    __syncthreads();

    const int h    = t & 1;          // state half
    const int role = (t >> 1) & 1;   // 0 = Q, 1 = V
    const int sid  = t >> 2;         // sample within block
    const int sidc = min(sid, rows - 1);

    // ---- pre-linear: 24 elements per lane, butterfly-reduce over 4 lanes ----
    const int k0 = (t & 3) * 6;      // float4 offset of this lane's chunk
    float acc[4] = {0.f, 0.f, 0.f, 0.f};
    #pragma unroll
    for (int k = 0; k < 6; ++k) {
        float4 v = *reinterpret_cast<const float4*>(&tile[sidc][4 * (k0 + k)]);
        #pragma unroll
        for (int o = 0; o < 4; ++o) {
            float4 w = *reinterpret_cast<const float4*>(&wsh[96 * o + 4 * (k0 + k)]);
            acc[o] += v.x * w.x + v.y * w.y + v.z * w.z + v.w * w.w;
        }
    }
    float ec[4], es[4];
    #pragma unroll
    for (int o = 0; o < 4; ++o) {
        float part = acc[o];
        part += __shfl_xor_sync(0xffffffffu, part, 1);
        part += __shfl_xor_sync(0xffffffffu, part, 2);
        __sincosf(0.5f * (part + pre_b[o]), &es[o], &ec[o]);
    }

    // ---- half of the product state after RX embed ----
    Cx p[8];
    #pragma unroll
    for (int j = 0; j < 8; ++j) {
        float m = (h ? es[0] : ec[0]) * ((j & 4) ? es[1] : ec[1])
                * ((j & 2) ? es[2] : ec[2]) * ((j & 1) ? es[3] : ec[3]);
        int k = (h + __popc(j)) & 3;             // (-i)^k
        p[j] = (k == 0) ? Cx{m, 0.f} : (k == 1) ? Cx{0.f, -m}
             : (k == 2) ? Cx{-m, 0.f} : Cx{0.f, m};
    }

    // ---- role circuit ----
    init_qkv_split(p, role ? sg[2] : sg[0], h);

    // second RX embed: Q lanes real angles, V lanes identity
    {
        float c0 = role ? 1.f : ec[0], s0 = role ? 0.f : es[0];
        float c1 = role ? 1.f : ec[1], s1 = role ? 0.f : es[1];
        float c2 = role ? 1.f : ec[2], s2 = role ? 0.f : es[2];
        float c3 = role ? 1.f : ec[3], s3 = role ? 0.f : es[3];
        rx_w0(p, c0, s0);
        rx_local<1>(p, c1, s1); rx_local<2>(p, c2, s2); rx_local<3>(p, c3, s3);
    }

    // measurement (valid on Q lanes; V lanes lockstep don't-care)
    float zq[4], xq[4];
    measZX_split(p, h, zq, xq);

    // score -> RZ half-angle (c,s); broadcast Q-lane values to the V pair
    float scc[4], scs[4];
    #pragma unroll
    for (int w = 0; w < 4; ++w) {
        float m  = xq[w] * sxk[w];
        float sc = sqrtf(zq[w]*zq[w] + m*m);
        float e  = __expf(2.f * sc);                  // tanh(sc), sc >= 0
        float th = __fdividef(e - 1.f, e + 1.f);
        __sincosf(th * (0.5f * PI_F), &scs[w], &scc[w]);
        scc[w] = __shfl_xor_sync(0xffffffffu, scc[w], 2);  // role partner
        scs[w] = __shfl_xor_sync(0xffffffffu, scs[w], 2);
        // after xor2, V lanes hold Q values (Q lanes hold V garbage - unused)
    }

    // ---- V tail (Q lanes lockstep don't-care) ----
    rz0(p, scc[0], scs[0], h);
    rz_local<1>(p, scc[1], scs[1]);
    rz_local<2>(p, scc[2], scs[2]);
    rz_local<3>(p, scc[3], scs[3]);
    cnot_ctrl0<1>(p, h);
    cnot_local<1,2>(p);
    cnot_local<2,3>(p);

    float o[8];
    {
        float z[4], x[4];
        measZX_split(p, h, z, x);
        o[0]=z[0]; o[1]=z[1]; o[2]=z[2]; o[3]=z[3];
        o[4]=x[0]; o[5]=x[1]; o[6]=x[2]; o[7]=x[3];
    }

    // ---- LayerNorm(8) + exact GELU + head ----
    float mu = 0.f;
    #pragma unroll
    for (int k = 0; k < 8; ++k) mu += o[k];
    mu *= 0.125f;
    float var = 0.f;
    #pragma unroll
    for (int k = 0; k < 8; ++k) { float d = o[k] - mu; var += d * d; }
    var *= 0.125f;
    float inv = rsqrtf(var + 1e-5f);

    float r0 = head_b[0], r1 = head_b[1];
    #pragma unroll
    for (int k = 0; k < 8; ++k) {
        float y = (o[k] - mu) * inv * ln_w[k] + ln_b[k];
        float g = 0.5f * y * (1.f + erff(y * 0.70710678118654752f));
        r0 += g * head_w[k];
        r1 += g * head_w[8 + k];
    }

    if ((t & 3) == 2 && sid < rows)   // V role, h=0 lane writes
        *reinterpret_cast<float2*>(out + 2 * (base + sid)) = make_float2(r0, r1);
}

extern "C" void kernel_launch(void* const* d_in, const int* in_sizes, int n_in,
                              void* d_out, int out_size) {
    const float* x1     = (const float*)d_in[0];
    const float* pre_w  = (const float*)d_in[1];
    const float* pre_b  = (const float*)d_in[2];
    const float* q_rot  = (const float*)d_in[3];
    const float* k_rot  = (const float*)d_in[4];
    const float* v_rot  = (const float*)d_in[5];
    const float* q_crx  = (const float*)d_in[6];
    const float* k_crx  = (const float*)d_in[7];
    const float* v_crx  = (const float*)d_in[8];
    const float* ln_w   = (const float*)d_in[9];
    const float* ln_b   = (const float*)d_in[10];
    const float* head_w = (const float*)d_in[11];
    const float* head_b = (const float*)d_in[12];
    int B = in_sizes[0] / 96;

    qc_quad<<<(B + SROWS - 1) / SROWS, TPB>>>(x1, pre_w, pre_b,
                                              q_rot, k_rot, v_rot,
                                              q_crx, k_crx, v_crx,
                                              ln_w, ln_b, head_w, head_b,
                                              (float*)d_out, B);
}

// round 8
// speedup vs baseline: 1.1805x; 1.1805x over previous
#include <cuda_runtime.h>

// ---------------------------------------------------------------------------
// QuantumClassifier: 2 lanes per sample (even=Q circuit, odd=V circuit),
// fully convergent; score crosses via SHFL.
// R7 changes vs the 12.8us version:
//  - gate tables stage-major (12 floats, 16B aligned): whole role table
//    (8 stages) batch-preloaded into registers before the circuit -> LDS
//    latency off the FMA chain.
//  - SROWS=112 / TPB=224 -> 147 blocks ~= one 7-warp block per SM,
//    balanced single wave (was 256 blocks: 8-warp/4-warp SM imbalance).
// ---------------------------------------------------------------------------

struct Cx { float r, i; };
struct SC { Cx u0, u1, u2, u3; float c, s; };   // one Rot+CRX stage

#define PI_F  3.14159265358979f
#define SROWS 112     // samples per block
#define TPB   224     // 2 threads per sample, 7 warps

// ---- full-state (16 amp) primitives: used only for the constant-K sim ----
template<int W>
__device__ __forceinline__ void ap1g(Cx* p, Cx u0, Cx u1, Cx u2, Cx u3) {
    constexpr int s = 8 >> W;
    #pragma unroll
    for (int i = 0; i < 16; ++i) if (!(i & s)) {
        Cx a = p[i], b = p[i + s];
        p[i]   = Cx{ u0.r*a.r - u0.i*a.i + u1.r*b.r - u1.i*b.i,
                     u0.r*a.i + u0.i*a.r + u1.r*b.i + u1.i*b.r };
        p[i+s] = Cx{ u2.r*a.r - u2.i*a.i + u3.r*b.r - u3.i*b.i,
                     u2.r*a.i + u2.i*a.r + u3.r*b.i + u3.i*b.r };
    }
}
template<int A, int B>
__device__ __forceinline__ void crxg(Cx* p, float c, float s) {
    constexpr int sa = 8 >> A, sb = 8 >> B;
    #pragma unroll
    for (int i = 0; i < 16; ++i) if ((i & sa) && !(i & sb)) {
        Cx a = p[i], b = p[i + sb];
        p[i]    = Cx{ c*a.r + s*b.i, c*a.i - s*b.r };
        p[i+sb] = Cx{ c*b.r + s*a.i, c*b.i - s*a.r };
    }
}
template<int A, int B>
__device__ __forceinline__ void cnotg(Cx* p) {
    constexpr int sa = 8 >> A, sb = 8 >> B;
    #pragma unroll
    for (int i = 0; i < 16; ++i) if ((i & sa) && !(i & sb)) {
        Cx t = p[i]; p[i] = p[i + sb]; p[i + sb] = t;
    }
}
// RX butterfly
template<int W>
__device__ __forceinline__ void rxg(Cx* p, float c, float s) {
    constexpr int st = 8 >> W;
    #pragma unroll
    for (int i = 0; i < 16; ++i) if (!(i & st)) {
        Cx a = p[i], b = p[i + st];
        p[i]    = Cx{ c*a.r + s*b.i, c*a.i - s*b.r };
        p[i+st] = Cx{ c*b.r + s*a.i, c*b.i - s*a.r };
    }
}
// RZ(t)
template<int W>
__device__ __forceinline__ void rzg(Cx* p, float c, float s) {
    constexpr int st = 8 >> W;
    #pragma unroll
    for (int i = 0; i < 16; ++i) {
        Cx a = p[i];
        float ss = (i & st) ? s : -s;
        p[i] = Cx{ c*a.r - ss*a.i, c*a.i + ss*a.r };
    }
}
// all 4 <Z_w>, <X_w>
__device__ __forceinline__ void measZX(const Cx* p, float* z, float* x) {
    float mag[16];
    #pragma unroll
    for (int i = 0; i < 16; ++i) mag[i] = p[i].r*p[i].r + p[i].i*p[i].i;
    #pragma unroll
    for (int w = 0; w < 4; ++w) {
        const int st = 8 >> w;
        float zz = 0.f, xx = 0.f;
        #pragma unroll
        for (int i = 0; i < 16; ++i) zz += (i & st) ? -mag[i] : mag[i];
        #pragma unroll
        for (int i = 0; i < 16; ++i) if (!(i & st))
            xx += p[i].r*p[i+st].r + p[i].i*p[i+st].i;
        z[w] = zz; x[w] = 2.f * xx;
    }
}

// ---- stage-major gate table: stage i at g[12*i]: u00,u01,u10,u11 (8f), c, s ----
__device__ __forceinline__ SC load_sc(const float* g, int i) {
    float4 a = *reinterpret_cast<const float4*>(g + 12*i);
    float4 b = *reinterpret_cast<const float4*>(g + 12*i + 4);
    float2 cs = *reinterpret_cast<const float2*>(g + 12*i + 8);
    return SC{ Cx{a.x, a.y}, Cx{a.z, a.w}, Cx{b.x, b.y}, Cx{b.z, b.w}, cs.x, cs.y };
}

template<int A, int B>
__device__ __forceinline__ void stage(Cx* p, const SC& sc) {
    ap1g<A>(p, sc.u0, sc.u1, sc.u2, sc.u3);
    crxg<A, B>(p, sc.c, sc.s);
    cnotg<A, B>(p);
}

// wire-pair order: (0,1)(1,2)(2,3)(3,0)(0,3)(1,0)(2,1)(3,2)
// batch-preload all 8 stages (80 regs), then pure-FMA circuit
__device__ __forceinline__ void init_qkv(Cx* p, const float* g) {
    SC s0 = load_sc(g, 0), s1 = load_sc(g, 1), s2 = load_sc(g, 2), s3 = load_sc(g, 3);
    SC s4 = load_sc(g, 4), s5 = load_sc(g, 5), s6 = load_sc(g, 6), s7 = load_sc(g, 7);
    stage<0,1>(p, s0); stage<1,2>(p, s1); stage<2,3>(p, s2); stage<3,0>(p, s3);
    stage<0,3>(p, s4); stage<1,0>(p, s5); stage<2,1>(p, s6); stage<3,2>(p, s7);
}

// one Rot+CRX stage of a gate table (stage-major layout)
__device__ __forceinline__ void build_stage(const float* rot, const float* crx,
                                            int s, float* g) {
    float phi = rot[3*s], th = rot[3*s+1], om = rot[3*s+2];
    float sa, ca, sb, cb, st2, ct2;
    sincosf(0.5f*(phi+om), &sa, &ca);
    sincosf(0.5f*(phi-om), &sb, &cb);
    sincosf(0.5f*th, &st2, &ct2);
    float* q = g + 12*s;
    q[0] =  ca*ct2; q[1] = -sa*ct2;   // u00 = e^{-iA} cos
    q[2] = -cb*st2; q[3] = -sb*st2;   // u01 = -e^{+iB} sin
    q[4] =  cb*st2; q[5] = -sb*st2;   // u10 = e^{-iB} sin
    q[6] =  ca*ct2; q[7] =  sa*ct2;   // u11 = e^{+iA} cos
    float cc, sc; sincosf(0.5f*crx[s], &sc, &cc);
    q[8] = cc; q[9] = sc; q[10] = 0.f; q[11] = 0.f;
}

__global__ void __launch_bounds__(TPB)
qc_pair(const float* __restrict__ x1,
        const float* __restrict__ pre_w, const float* __restrict__ pre_b,
        const float* __restrict__ q_rot, const float* __restrict__ k_rot,
        const float* __restrict__ v_rot,
        const float* __restrict__ q_crx, const float* __restrict__ k_crx,
        const float* __restrict__ v_crx,
        const float* __restrict__ ln_w, const float* __restrict__ ln_b,
        const float* __restrict__ head_w, const float* __restrict__ head_b,
        float* __restrict__ out, int B)
{
    __shared__ __align__(16) float sg[3][96];        // Q / K / V, stage-major
    __shared__ float sxk[4];                         // <X_w> of constant K state
    __shared__ __align__(16) float wsh[384];         // pre_w
    __shared__ __align__(16) float tile[SROWS][100]; // x1 tile (pad 100)

    const int t = threadIdx.x;
    const int base = blockIdx.x * SROWS;
    const int rows = min(SROWS, B - base);

    if (t >= 192) {
        // warp 6: K table -> K simulation -> sxk (overlaps warps 0-5)
        if (t < 200) build_stage(k_rot, k_crx, t - 192, sg[1]);
        __syncwarp();
        if (t == 192) {
            Cx p[16];
            #pragma unroll
            for (int i = 0; i < 16; ++i) p[i] = Cx{0.f, 0.f};
            p[0] = Cx{1.f, 0.f};
            init_qkv(p, sg[1]);
            float z[4], xk[4];
            measZX(p, z, xk);
            sxk[0] = xk[0]; sxk[1] = xk[1]; sxk[2] = xk[2]; sxk[3] = xk[3];
        }
    } else {
        if (t < 16) {
            int c = t >> 3, s = t & 7;            // c=0 -> Q, c=1 -> V
            build_stage(c ? v_rot : q_rot, c ? v_crx : q_crx, s, sg[c ? 2 : 0]);
        }
        // stage x1 tile (coalesced float4) + pre_w, threads 0..191
        const float4* x4 = reinterpret_cast<const float4*>(x1 + (size_t)base * 96);
        for (int f = t; f < rows * 24; f += 192) {
            float4 v = x4[f];
            int r = f / 24, c = f % 24;
            *reinterpret_cast<float4*>(&tile[r][4 * c]) = v;
        }
        for (int e = t; e < 384; e += 192) wsh[e] = pre_w[e];
    }
    __syncthreads();

    const int sid  = t >> 1;                 // sample within block
    const int sidc = min(sid, rows - 1);     // clamp (keeps warp convergent)
    const bool isQ = !(t & 1);

    // ---- pre-linear, split 48/48 across the lane pair ----
    const int k0 = (t & 1) * 12;             // float4 offset for this lane
    float ax[4] = {0,0,0,0}, ay[4] = {0,0,0,0}, az[4] = {0,0,0,0}, aw[4] = {0,0,0,0};
    #pragma unroll
    for (int k = 0; k < 12; ++k) {
        float4 v = *reinterpret_cast<const float4*>(&tile[sidc][4 * (k0 + k)]);
        #pragma unroll
        for (int o = 0; o < 4; ++o) {
            float4 w = *reinterpret_cast<const float4*>(&wsh[96 * o + 4 * (k0 + k)]);
            ax[o] += v.x * w.x; ay[o] += v.y * w.y;
            az[o] += v.z * w.z; aw[o] += v.w * w.w;
        }
    }
    float ec[4], es[4];
    #pragma unroll
    for (int o = 0; o < 4; ++o) {
        float part = (ax[o] + ay[o]) + (az[o] + aw[o]);
        float xv = part + __shfl_xor_sync(0xffffffffu, part, 1) + pre_b[o];
        __sincosf(0.5f * xv, &es[o], &ec[o]);
    }

    // ---- product state after RX embed: amp[i] = (-i)^popc * prod(c/s) ----
    Cx p[16];
    #pragma unroll
    for (int i = 0; i < 16; ++i) {
        float m = ((i & 8) ? es[0] : ec[0]) * ((i & 4) ? es[1] : ec[1])
                * ((i & 2) ? es[2] : ec[2]) * ((i & 1) ? es[3] : ec[3]);
        int k = __popc(i) & 3;
        p[i] = (k == 0) ? Cx{m, 0.f} : (k == 1) ? Cx{0.f, -m}
             : (k == 2) ? Cx{-m, 0.f} : Cx{0.f, m};
    }

    // ---- role circuit: even lane -> Q table, odd lane -> V table ----
    init_qkv(p, isQ ? sg[0] : sg[2]);

    // second RX embed: Q uses real angles, V uses identity
    {
        float c0 = isQ ? ec[0] : 1.f, s0 = isQ ? es[0] : 0.f;
        float c1 = isQ ? ec[1] : 1.f, s1 = isQ ? es[1] : 0.f;
        float c2 = isQ ? ec[2] : 1.f, s2 = isQ ? es[2] : 0.f;
        float c3 = isQ ? ec[3] : 1.f, s3 = isQ ? es[3] : 0.f;
        rxg<0>(p, c0, s0); rxg<1>(p, c1, s1); rxg<2>(p, c2, s2); rxg<3>(p, c3, s3);
    }

    // measurement (valid for Q lanes; V lanes lockstep don't-care)
    float zq[4], xq[4];
    measZX(p, zq, xq);

    // score -> RZ half-angle (c,s); broadcast Q-lane values to the pair
    float scc[4], scs[4];
    #pragma unroll
    for (int w = 0; w < 4; ++w) {
        float m  = xq[w] * sxk[w];
        float sc = sqrtf(zq[w]*zq[w] + m*m);
        float e  = __expf(2.f * sc);                  // tanh(sc), sc >= 0
        float th = __fdividef(e - 1.f, e + 1.f);
        __sincosf(th * (0.5f * PI_F), &scs[w], &scc[w]);
    }
    const int src = (t & 31) & ~1;
    #pragma unroll
    for (int w = 0; w < 4; ++w) {
        scc[w] = __shfl_sync(0xffffffffu, scc[w], src);
        scs[w] = __shfl_sync(0xffffffffu, scs[w], src);
    }

    // ---- V tail (Q lanes lockstep don't-care) ----
    rzg<0>(p, scc[0], scs[0]); rzg<1>(p, scc[1], scs[1]);
    rzg<2>(p, scc[2], scs[2]); rzg<3>(p, scc[3], scs[3]);
    cnotg<0,1>(p); cnotg<1,2>(p); cnotg<2,3>(p);

    float o[8];
    {
        float z[4], x[4];
        measZX(p, z, x);
        o[0]=z[0]; o[1]=z[1]; o[2]=z[2]; o[3]=z[3];
        o[4]=x[0]; o[5]=x[1]; o[6]=x[2]; o[7]=x[3];
    }

    // ---- LayerNorm(8) + exact GELU + head ----
    float mu = 0.f;
    #pragma unroll
    for (int k = 0; k < 8; ++k) mu += o[k];
    mu *= 0.125f;
    float var = 0.f;
    #pragma unroll
    for (int k = 0; k < 8; ++k) { float d = o[k] - mu; var += d * d; }
    var *= 0.125f;
    float inv = rsqrtf(var + 1e-5f);

    float r0 = head_b[0], r1 = head_b[1];
    #pragma unroll
    for (int k = 0; k < 8; ++k) {
        float y = (o[k] - mu) * inv * ln_w[k] + ln_b[k];
        float g = 0.5f * y * (1.f + erff(y * 0.70710678118654752f));
        r0 += g * head_w[k];
        r1 += g * head_w[8 + k];
    }

    if ((t & 1) && sid < rows)   // odd (V) lane holds the valid result
        *reinterpret_cast<float2*>(out + 2 * (base + sid)) = make_float2(r0, r1);
}

extern "C" void kernel_launch(void* const* d_in, const int* in_sizes, int n_in,
                              void* d_out, int out_size) {
    const float* x1     = (const float*)d_in[0];
    const float* pre_w  = (const float*)d_in[1];
    const float* pre_b  = (const float*)d_in[2];
    const float* q_rot  = (const float*)d_in[3];
    const float* k_rot  = (const float*)d_in[4];
    const float* v_rot  = (const float*)d_in[5];
    const float* q_crx  = (const float*)d_in[6];
    const float* k_crx  = (const float*)d_in[7];
    const float* v_crx  = (const float*)d_in[8];
    const float* ln_w   = (const float*)d_in[9];
    const float* ln_b   = (const float*)d_in[10];
    const float* head_w = (const float*)d_in[11];
    const float* head_b = (const float*)d_in[12];
    int B = in_sizes[0] / 96;

    qc_pair<<<(B + SROWS - 1) / SROWS, TPB>>>(x1, pre_w, pre_b,
                                              q_rot, k_rot, v_rot,
                                              q_crx, k_crx, v_crx,
                                              ln_w, ln_b, head_w, head_b,
                                              (float*)d_out, B);
}